// round 5
// baseline (speedup 1.0000x reference)
#include <cuda_runtime.h>
#include <cuda_bf16.h>
#include <math.h>

#define Bz 32
#define Sz 64
#define Tz 32
#define Ez 300
#define HEz 256
#define HDz 512
#define VDz 50000
#define XAz (Ez + 2*HEz)      /* 812: [emb, h] / [emb, ctx] */
#define XTz (XAz + HDz)       /* 1324 */
#define NCHUNK 98             /* ceil(50000/512) */
#define K5_VPB 512

// ---------------- device scratch (static, no allocation) ----------------
__device__ __align__(16) float g_X[Sz*Bz*Ez];
__device__ __align__(16) float g_GI[2][Sz*Bz*3*HEz];
__device__ __align__(16) float g_h[2][2][Bz*HEz];     // [dir][parity]
__device__ __align__(16) float g_enc[Bz*Sz*2*HEz];
__device__ __align__(16) float g_hd[2][Bz*HDz];       // decoder hidden ping-pong
__device__ __align__(16) float g_q[Bz*2*HEz];
__device__ __align__(16) float g_ctx[Bz*2*HEz];
__device__ int   g_inp[Bz];
__device__ int   g_idx[Bz*Tz];
__device__ unsigned long long g_amax[Bz];
__device__ float g_psum[Bz*256];
__device__ float g_logZ[Tz*Bz];

__device__ __forceinline__ float sigm(float x) { return 1.f / (1.f + expf(-x)); }

// ---------------- zero recurrent initial state (must rerun every call) ----
__global__ void k_zero() {
    int i = blockIdx.x * blockDim.x + threadIdx.x;
    if (i < Bz*HEz) { g_h[0][0][i] = 0.f; g_h[1][0][i] = 0.f; }
}

// ---------------- encoder embedding gather:  g_X[s][b][e] ----------------
__global__ void k_embed_enc(const int* __restrict__ data, const float* __restrict__ emb) {
    int i = blockIdx.x * 256 + threadIdx.x;
    if (i >= Sz*Bz*Ez) return;
    int e = i % Ez; int sb = i / Ez; int b = sb % Bz; int s = sb / Bz;
    g_X[i] = emb[(long)data[b*Sz + s]*Ez + e];
}

// ---------------- batched input-gate GEMM for both directions ------------
// gi[s][b][j] = bih[j] + sum_e X[s][b][e] * Wih[j][e]
// dir 1 is stored indexed by BACKWARD step: g_GI[1][sb] holds gi(x[S-1-sb])
__global__ void k_gi(const float* __restrict__ Wf, const float* __restrict__ bf,
                     const float* __restrict__ Wb, const float* __restrict__ bb) {
    int s = blockIdx.y, dir = blockIdx.z;
    int b = threadIdx.x;
    int j = blockIdx.x * 8 + threadIdx.y;
    __shared__ float xs[Bz][Ez + 1];
    for (int i = threadIdx.y*32 + threadIdx.x; i < Bz*Ez; i += 256)
        xs[i / Ez][i % Ez] = g_X[(s*Bz)*Ez + i];
    __syncthreads();
    const float* W  = dir ? Wb : Wf;
    const float* bi = dir ? bb : bf;
    const float* wr = W + (long)j * Ez;
    float acc = bi[j];
    #pragma unroll 4
    for (int e = 0; e < Ez; e++) acc = fmaf(wr[e], xs[b][e], acc);
    int sd = dir ? (Sz - 1 - s) : s;
    g_GI[dir][((long)sd*Bz + b)*3*HEz + j] = acc;
}

// ---------------- one recurrent encoder step, both directions ------------
__global__ void k_enc_step(int s, const float* __restrict__ Whhf, const float* __restrict__ bhhf,
                           const float* __restrict__ Whhb, const float* __restrict__ bhhb) {
    int dir = blockIdx.y;
    int b = threadIdx.x;
    int u = blockIdx.x * 8 + threadIdx.y;
    int par = s & 1;
    __shared__ float hs[Bz][HEz + 1];
    const float* hprev = g_h[dir][par];
    for (int i = threadIdx.y*32 + threadIdx.x; i < Bz*HEz; i += 256)
        hs[i / HEz][i % HEz] = hprev[i];
    __syncthreads();
    const float* Whh = dir ? Whhb : Whhf;
    const float* bhh = dir ? bhhb : bhhf;
    const float* GI  = &g_GI[dir][((long)s*Bz + b)*3*HEz];
    float ar = GI[u]        + bhh[u];
    float az = GI[u + HEz]  + bhh[u + HEz];
    float an = bhh[u + 2*HEz];
    const float* w_r = Whh + (long)u*HEz;
    const float* w_z = Whh + (long)(u + HEz)*HEz;
    const float* w_n = Whh + (long)(u + 2*HEz)*HEz;
    #pragma unroll 8
    for (int c = 0; c < HEz; c++) {
        float hv = hs[b][c];
        ar = fmaf(w_r[c], hv, ar);
        az = fmaf(w_z[c], hv, az);
        an = fmaf(w_n[c], hv, an);
    }
    float r = sigm(ar), z = sigm(az);
    float n = tanhf(GI[u + 2*HEz] + r * an);
    float hn = (1.f - z) * n + z * hs[b][u];
    g_h[dir][par ^ 1][b*HEz + u] = hn;
    int sd = dir ? (Sz - 1 - s) : s;
    g_enc[((long)b*Sz + sd)*2*HEz + dir*HEz + u] = hn;
}

// ---------------- decoder init: h_dec = [hf_final, hb_final], inp = SOS ---
__global__ void k_dec_init() {
    int b = blockIdx.x, k = threadIdx.x;
    int fpar = Sz & 1;   // 0
    g_hd[0][b*HDz + k] = (k < HEz) ? g_h[0][fpar][b*HEz + k]
                                   : g_h[1][fpar][b*HEz + (k - HEz)];
    if (k == 0) g_inp[b] = 2;  // SOS
}

// ---------------- q = Wattn @ [emb, h] + battn  (all b in smem) ----------
__global__ void k_attn_q(const float* __restrict__ emb_dec, const float* __restrict__ Wattn,
                         const float* __restrict__ battn, int par) {
    extern __shared__ float xs[];
    const int LD = XAz + 1;
    int b = threadIdx.x;
    int j = blockIdx.x * 8 + threadIdx.y;
    for (int i = threadIdx.y*32 + threadIdx.x; i < Bz*XAz; i += 256) {
        int bb_ = i / XAz, k = i % XAz;
        float v = (k < Ez) ? emb_dec[(long)g_inp[bb_]*Ez + k]
                           : g_hd[par][bb_*HDz + (k - Ez)];
        xs[bb_*LD + k] = v;
    }
    __syncthreads();
    const float* w = Wattn + (long)j * XAz;
    const float* x = xs + b*LD;
    float acc = battn[j];
    #pragma unroll 4
    for (int k = 0; k < XAz; k++) acc = fmaf(w[k], x[k], acc);
    g_q[b*2*HEz + j] = acc;
}

// ---------------- attention scores + softmax + ctx, per-batch block ------
__global__ void k_attn_ctx(float* __restrict__ out_att, int t) {
    int b = blockIdx.x, tid = threadIdx.x;
    __shared__ float qs[2*HEz];
    __shared__ float sc[Sz];
    __shared__ float red;
    qs[tid]       = g_q[b*2*HEz + tid];
    qs[tid + 256] = g_q[b*2*HEz + tid + 256];
    if (tid == 0) g_amax[b] = 0ull;   // reset packed argmax for this step
    __syncthreads();
    if (tid < Sz) {
        const float* enc = g_enc + ((long)b*Sz + tid)*2*HEz;
        float a = 0.f;
        #pragma unroll 4
        for (int c = 0; c < 2*HEz; c++) a = fmaf(qs[c], enc[c], a);
        sc[tid] = a;
    }
    __syncthreads();
    if (tid == 0) {
        float m = sc[0];
        for (int i = 1; i < Sz; i++) m = fmaxf(m, sc[i]);
        red = m;
    }
    __syncthreads();
    if (tid < Sz) sc[tid] = expf(sc[tid] - red);
    __syncthreads();
    if (tid == 0) {
        float ssum = 0.f;
        for (int i = 0; i < Sz; i++) ssum += sc[i];
        red = 1.f / ssum;
    }
    __syncthreads();
    if (tid < Sz) {
        sc[tid] *= red;
        out_att[((long)b*Tz + t)*Sz + tid] = sc[tid];
    }
    __syncthreads();
    for (int c = tid; c < 2*HEz; c += 256) {
        float a = 0.f;
        for (int s2 = 0; s2 < Sz; s2++)
            a = fmaf(sc[s2], g_enc[((long)b*Sz + s2)*2*HEz + c], a);
        g_ctx[b*2*HEz + c] = a;
    }
}

// ---------------- decoder GRU cell (all b in smem) -----------------------
__global__ void k_dec_gru(const float* __restrict__ emb_dec, const float* __restrict__ Wihd,
                          const float* __restrict__ Whhd, const float* __restrict__ bihd,
                          const float* __restrict__ bhhd, int par) {
    extern __shared__ float xs[];
    const int LD = XTz + 1;   // 1325
    int b = threadIdx.x;
    int k = blockIdx.x * 8 + threadIdx.y;
    for (int i = threadIdx.y*32 + threadIdx.x; i < Bz*XTz; i += 256) {
        int bb_ = i / XTz, c = i % XTz;
        float v;
        if (c < Ez)        v = emb_dec[(long)g_inp[bb_]*Ez + c];
        else if (c < XAz)  v = g_ctx[bb_*2*HEz + (c - Ez)];
        else               v = g_hd[par][bb_*HDz + (c - XAz)];
        xs[bb_*LD + c] = v;
    }
    __syncthreads();
    float ar  = bihd[k] + bhhd[k];
    float az  = bihd[k + HDz] + bhhd[k + HDz];
    float ani = bihd[k + 2*HDz];
    float anh = bhhd[k + 2*HDz];
    const float* x  = xs + b*LD;
    const float* wr = Wihd + (long)k*XAz;
    const float* wz = Wihd + (long)(k + HDz)*XAz;
    const float* wn = Wihd + (long)(k + 2*HDz)*XAz;
    #pragma unroll 4
    for (int c = 0; c < XAz; c++) {
        float xv = x[c];
        ar  = fmaf(wr[c], xv, ar);
        az  = fmaf(wz[c], xv, az);
        ani = fmaf(wn[c], xv, ani);
    }
    const float* hr = Whhd + (long)k*HDz;
    const float* hz = Whhd + (long)(k + HDz)*HDz;
    const float* hn = Whhd + (long)(k + 2*HDz)*HDz;
    const float* xh = x + XAz;
    #pragma unroll 4
    for (int c = 0; c < HDz; c++) {
        float hv = xh[c];
        ar  = fmaf(hr[c], hv, ar);
        az  = fmaf(hz[c], hv, az);
        anh = fmaf(hn[c], hv, anh);
    }
    float r = sigm(ar), z = sigm(az);
    float n = tanhf(ani + r * anh);
    g_hd[par ^ 1][b*HDz + k] = (1.f - z) * n + z * xh[k];
}

// ---------------- output projection + exp-sum + packed argmax -------------
// lane-striped K, h2 in registers, coalesced Wout LDG.128; FFMA-bound.
__global__ void k_out_gemm(const float* __restrict__ Wout, const float* __restrict__ bout,
                           float* __restrict__ out_logp, int t, int par) {
    int b = blockIdx.y;
    int v0 = blockIdx.x * K5_VPB;
    int warp = threadIdx.x >> 5, lane = threadIdx.x & 31;
    const float4* h4 = (const float4*)(g_hd[par ^ 1] + b*HDz);
    float4 hreg[4];
    #pragma unroll
    for (int j = 0; j < 4; j++) hreg[j] = h4[j*32 + lane];

    __shared__ float sl[K5_VPB];
    for (int i = 0; i < 64; i++) {
        int v = v0 + warp*64 + i;
        float a0 = 0.f, a1 = 0.f, a2 = 0.f, a3 = 0.f;
        if (v < VDz) {
            const float4* w4 = (const float4*)(Wout + (long)v*HDz);
            float4 w;
            w = w4[0*32 + lane]; a0 = fmaf(w.x, hreg[0].x, a0); a1 = fmaf(w.y, hreg[0].y, a1);
                                 a2 = fmaf(w.z, hreg[0].z, a2); a3 = fmaf(w.w, hreg[0].w, a3);
            w = w4[1*32 + lane]; a0 = fmaf(w.x, hreg[1].x, a0); a1 = fmaf(w.y, hreg[1].y, a1);
                                 a2 = fmaf(w.z, hreg[1].z, a2); a3 = fmaf(w.w, hreg[1].w, a3);
            w = w4[2*32 + lane]; a0 = fmaf(w.x, hreg[2].x, a0); a1 = fmaf(w.y, hreg[2].y, a1);
                                 a2 = fmaf(w.z, hreg[2].z, a2); a3 = fmaf(w.w, hreg[2].w, a3);
            w = w4[3*32 + lane]; a0 = fmaf(w.x, hreg[3].x, a0); a1 = fmaf(w.y, hreg[3].y, a1);
                                 a2 = fmaf(w.z, hreg[3].z, a2); a3 = fmaf(w.w, hreg[3].w, a3);
        }
        float a = (a0 + a1) + (a2 + a3);
        a += __shfl_xor_sync(0xffffffffu, a, 16);
        a += __shfl_xor_sync(0xffffffffu, a, 8);
        a += __shfl_xor_sync(0xffffffffu, a, 4);
        a += __shfl_xor_sync(0xffffffffu, a, 2);
        a += __shfl_xor_sync(0xffffffffu, a, 1);
        if (lane == 0) sl[warp*64 + i] = a + ((v < VDz) ? bout[v] : 0.f);
    }
    __syncthreads();

    float* outp = out_logp + ((long)(b*Tz + t))*VDz + v0;
    float esum = 0.f;
    unsigned long long pk = 0ull;
    for (int i = threadIdx.x; i < K5_VPB; i += 256) {
        int v = v0 + i;
        if (v < VDz) {
            float lg = sl[i];
            outp[i] = lg;                      // raw logit; logZ subtracted later
            esum += expf(lg);
            unsigned u = __float_as_uint(lg);
            u = (u & 0x80000000u) ? ~u : (u | 0x80000000u);   // monotone map
            unsigned long long p = ((unsigned long long)u << 32)
                                 | (unsigned long long)(0xFFFFFFFFu - (unsigned)v);
            pk = (p > pk) ? p : pk;
        }
    }
    __shared__ float rs[256];
    __shared__ unsigned long long rp[256];
    rs[threadIdx.x] = esum; rp[threadIdx.x] = pk;
    __syncthreads();
    for (int off = 128; off > 0; off >>= 1) {
        if (threadIdx.x < off) {
            rs[threadIdx.x] += rs[threadIdx.x + off];
            unsigned long long o = rp[threadIdx.x + off];
            if (o > rp[threadIdx.x]) rp[threadIdx.x] = o;
        }
        __syncthreads();
    }
    if (threadIdx.x == 0) {
        g_psum[b*256 + blockIdx.x] = rs[0];
        atomicMax(&g_amax[b], rp[0]);
    }
}

// ---------------- per-step finalize: logZ, argmax token -------------------
__global__ void k_finalize_step(int t) {
    int b = blockIdx.x;
    __shared__ float rs[256];
    rs[threadIdx.x] = (threadIdx.x < NCHUNK) ? g_psum[b*256 + threadIdx.x] : 0.f;
    __syncthreads();
    for (int off = 128; off > 0; off >>= 1) {
        if (threadIdx.x < off) rs[threadIdx.x] += rs[threadIdx.x + off];
        __syncthreads();
    }
    if (threadIdx.x == 0) {
        g_logZ[t*Bz + b] = logf(rs[0]);
        unsigned vv = 0xFFFFFFFFu - (unsigned)(g_amax[b] & 0xFFFFFFFFull);
        g_inp[b] = (int)vv;
        g_idx[b*Tz + t] = (int)vv;
    }
}

// ---------------- EOS mask + idx as float ---------------------------------
__global__ void k_mask(float* __restrict__ out_idx, float* __restrict__ out_mask) {
    int b = threadIdx.x;
    if (b >= Bz) return;
    int cnt = 0;
    for (int t = 0; t < Tz; t++) {
        int v = g_idx[b*Tz + t];
        cnt += (v == 3);
        out_idx[b*Tz + t]  = (float)v;
        out_mask[b*Tz + t] = (cnt == 0) ? 1.f : 0.f;
    }
}

// ---------------- final log-softmax normalization (one big pass) ----------
__global__ void k_logp_final(float* __restrict__ out_logp) {
    long i4 = (long)blockIdx.x * 256 + threadIdx.x;   // over B*T*VD/4
    long e0 = i4 * 4;
    int bt = (int)(e0 / VDz);
    int b = bt / Tz, t = bt % Tz;
    float lz = g_logZ[t*Bz + b];
    float4* p = (float4*)out_logp + i4;
    float4 v = *p;
    v.x -= lz; v.y -= lz; v.z -= lz; v.w -= lz;
    *p = v;
}

// =========================================================================
extern "C" void kernel_launch(void* const* d_in, const int* in_sizes, int n_in,
                              void* d_out, int out_size) {
    const int*   data    = (const int*)  d_in[0];
    const float* emb_enc = (const float*)d_in[4];
    const float* emb_dec = (const float*)d_in[5];
    const float* Wihf = (const float*)d_in[6],  *Whhf = (const float*)d_in[7];
    const float* bihf = (const float*)d_in[8],  *bhhf = (const float*)d_in[9];
    const float* Wihb = (const float*)d_in[10], *Whhb = (const float*)d_in[11];
    const float* bihb = (const float*)d_in[12], *bhhb = (const float*)d_in[13];
    const float* Wihd = (const float*)d_in[14], *Whhd = (const float*)d_in[15];
    const float* bihd = (const float*)d_in[16], *bhhd = (const float*)d_in[17];
    const float* Wattn = (const float*)d_in[18], *battn = (const float*)d_in[19];
    const float* Wout  = (const float*)d_in[20], *bout  = (const float*)d_in[21];

    float* out      = (float*)d_out;
    float* out_logp = out;                                   // [B,T,VD]
    float* out_idx  = out + (long)Bz*Tz*VDz;                 // [B,T]
    float* out_mask = out_idx + Bz*Tz;                       // [B,T]
    float* out_att  = out_mask + Bz*Tz;                      // [B,T,S]

    const int smemQ = Bz * (XAz + 1) * 4;    // 104,064 B
    const int smemG = Bz * (XTz + 1) * 4;    // 169,600 B
    cudaFuncSetAttribute(k_attn_q,  cudaFuncAttributeMaxDynamicSharedMemorySize, smemQ);
    cudaFuncSetAttribute(k_dec_gru, cudaFuncAttributeMaxDynamicSharedMemorySize, smemG);

    // ---- encoder ----
    k_zero<<<(Bz*HEz + 255)/256, 256>>>();
    k_embed_enc<<<(Sz*Bz*Ez + 255)/256, 256>>>(data, emb_enc);
    k_gi<<<dim3(96, Sz, 2), dim3(32, 8)>>>(Wihf, bihf, Wihb, bihb);
    for (int s = 0; s < Sz; s++)
        k_enc_step<<<dim3(32, 2), dim3(32, 8)>>>(s, Whhf, bhhf, Whhb, bhhb);
    k_dec_init<<<Bz, HDz>>>();

    // ---- decoder (greedy, argmax feedback) ----
    for (int t = 0; t < Tz; t++) {
        int par = t & 1;
        k_attn_q<<<64, dim3(32, 8), smemQ>>>(emb_dec, Wattn, battn, par);
        k_attn_ctx<<<Bz, 256>>>(out_att, t);
        k_dec_gru<<<64, dim3(32, 8), smemG>>>(emb_dec, Wihd, Whhd, bihd, bhhd, par);
        k_out_gemm<<<dim3(NCHUNK, Bz), 256>>>(Wout, bout, out_logp, t, par);
        k_finalize_step<<<Bz, 256>>>(t);
    }

    // ---- finalize outputs ----
    k_mask<<<1, 32>>>(out_idx, out_mask);
    k_logp_final<<<(int)(((long)Bz*Tz*VDz/4 + 255)/256), 256>>>(out_logp);
}

// round 8
// speedup vs baseline: 1.4572x; 1.4572x over previous
#include <cuda_runtime.h>
#include <cuda_bf16.h>
#include <math.h>

#define Bz 32
#define Sz 64
#define Tz 32
#define Ez 300
#define HEz 256
#define HDz 512
#define VDz 50000
#define XAz (Ez + 2*HEz)      /* 812 */
#define XTz (XAz + HDz)       /* 1324 */

// ---- k_out_gemm tiling ----
#define OG_ROWS 344           /* rows per block */
#define OG_NGRP 43            /* 43*8 = 344 */
#define OG_GRID 146           /* 146*344 = 50224 >= 50000 */

// ---------------- device scratch (static, no allocation) ----------------
__device__ __align__(16) float g_X[Sz*Bz*Ez];
__device__ __align__(16) float g_GI[2][Sz*Bz*3*HEz];
__device__ __align__(16) float g_h[2][2][Bz*HEz];     // [dir][parity]
__device__ __align__(16) float g_enc[Bz*Sz*2*HEz];
__device__ __align__(16) float g_hd[2][Bz*HDz];       // decoder hidden ping-pong
__device__ __align__(16) float g_q[Bz*2*HEz];
__device__ __align__(16) float g_ctx[Bz*2*HEz];
__device__ int   g_inp[Bz];
__device__ int   g_idx[Bz*Tz];
__device__ unsigned long long g_amax[Bz];
__device__ float g_esum[Bz];
__device__ float g_logZ[Tz*Bz];

__device__ __forceinline__ float sigm(float x) { return 1.f / (1.f + expf(-x)); }

__device__ __forceinline__ unsigned long long ffma2(unsigned long long a,
                                                    unsigned long long b,
                                                    unsigned long long c) {
    unsigned long long d;
    asm("fma.rn.f32x2 %0, %1, %2, %3;" : "=l"(d) : "l"(a), "l"(b), "l"(c));
    return d;
}

__device__ __forceinline__ void cpa16(unsigned int dst, const void* src) {
    asm volatile("cp.async.cg.shared.global [%0], [%1], 16;" :: "r"(dst), "l"(src));
}

// ---------------- zero recurrent initial state ----------------------------
__global__ void k_zero() {
    int i = blockIdx.x * blockDim.x + threadIdx.x;
    if (i < Bz*HEz) { g_h[0][0][i] = 0.f; g_h[1][0][i] = 0.f; }
}

// ---------------- encoder embedding gather --------------------------------
__global__ void k_embed_enc(const int* __restrict__ data, const float* __restrict__ emb) {
    int i = blockIdx.x * 256 + threadIdx.x;
    if (i >= Sz*Bz*Ez) return;
    int e = i % Ez; int sb = i / Ez; int b = sb % Bz; int s = sb / Bz;
    g_X[i] = emb[(long)data[b*Sz + s]*Ez + e];
}

// ---------------- batched input-gate GEMM, both directions ----------------
__global__ void k_gi(const float* __restrict__ Wf, const float* __restrict__ bf,
                     const float* __restrict__ Wb, const float* __restrict__ bb) {
    int s = blockIdx.y, dir = blockIdx.z;
    int b = threadIdx.x;
    int j = blockIdx.x * 8 + threadIdx.y;
    __shared__ float xs[Bz][308];
    int tid = threadIdx.y*32 + threadIdx.x;
    for (int i = tid; i < Bz*75; i += 256) {
        int b_ = i / 75, c4 = i % 75;
        *(float4*)&xs[b_][c4*4] = *(const float4*)&g_X[((long)s*Bz + b_)*Ez + c4*4];
    }
    __syncthreads();
    const float* W  = dir ? Wb : Wf;
    const float* bi = dir ? bb : bf;
    const float4* w4 = (const float4*)(W + (long)j * Ez);
    const float4* x4 = (const float4*)&xs[b][0];
    float a0 = bi[j], a1 = 0.f;
    #pragma unroll 4
    for (int c = 0; c < 74; c += 2) {
        float4 w = w4[c],   x = x4[c];
        a0 = fmaf(w.x,x.x,a0); a0 = fmaf(w.y,x.y,a0); a0 = fmaf(w.z,x.z,a0); a0 = fmaf(w.w,x.w,a0);
        float4 w2 = w4[c+1], x2 = x4[c+1];
        a1 = fmaf(w2.x,x2.x,a1); a1 = fmaf(w2.y,x2.y,a1); a1 = fmaf(w2.z,x2.z,a1); a1 = fmaf(w2.w,x2.w,a1);
    }
    { float4 w = w4[74], x = x4[74];
      a0 = fmaf(w.x,x.x,a0); a0 = fmaf(w.y,x.y,a0); a0 = fmaf(w.z,x.z,a0); a0 = fmaf(w.w,x.w,a0); }
    int sd = dir ? (Sz - 1 - s) : s;
    g_GI[dir][((long)sd*Bz + b)*3*HEz + j] = a0 + a1;
}

// ---------------- one recurrent encoder step, both directions -------------
// grid (64, 2), block (32, 4)
__global__ void k_enc_step(int s, const float* __restrict__ Whhf, const float* __restrict__ bhhf,
                           const float* __restrict__ Whhb, const float* __restrict__ bhhb) {
    int dir = blockIdx.y;
    int b = threadIdx.x;
    int u = blockIdx.x * 4 + threadIdx.y;
    int par = s & 1;
    __shared__ float hs[Bz][260];
    const float* hprev = g_h[dir][par];
    int tid = threadIdx.y*32 + threadIdx.x;
    for (int i = tid; i < Bz*HEz/4; i += 128) {
        int e = i*4;
        *(float4*)&hs[e / HEz][e % HEz] = *(const float4*)&hprev[e];
    }
    __syncthreads();
    const float* Whh = dir ? Whhb : Whhf;
    const float* bhh = dir ? bhhb : bhhf;
    const float* GI  = &g_GI[dir][((long)s*Bz + b)*3*HEz];
    float ar = GI[u]        + bhh[u];
    float az = GI[u + HEz]  + bhh[u + HEz];
    float an = bhh[u + 2*HEz];
    const float4* wr4 = (const float4*)(Whh + (long)u*HEz);
    const float4* wz4 = (const float4*)(Whh + (long)(u + HEz)*HEz);
    const float4* wn4 = (const float4*)(Whh + (long)(u + 2*HEz)*HEz);
    const float4* h4  = (const float4*)&hs[b][0];
    #pragma unroll 8
    for (int c = 0; c < 64; c++) {
        float4 hv = h4[c];
        float4 wr = wr4[c], wz = wz4[c], wn = wn4[c];
        ar = fmaf(wr.x,hv.x,ar); ar = fmaf(wr.y,hv.y,ar); ar = fmaf(wr.z,hv.z,ar); ar = fmaf(wr.w,hv.w,ar);
        az = fmaf(wz.x,hv.x,az); az = fmaf(wz.y,hv.y,az); az = fmaf(wz.z,hv.z,az); az = fmaf(wz.w,hv.w,az);
        an = fmaf(wn.x,hv.x,an); an = fmaf(wn.y,hv.y,an); an = fmaf(wn.z,hv.z,an); an = fmaf(wn.w,hv.w,an);
    }
    float r = sigm(ar), z = sigm(az);
    float n = tanhf(GI[u + 2*HEz] + r * an);
    float hn = (1.f - z) * n + z * hs[b][u];
    g_h[dir][par ^ 1][b*HEz + u] = hn;
    int sd = dir ? (Sz - 1 - s) : s;
    g_enc[((long)b*Sz + sd)*2*HEz + dir*HEz + u] = hn;
}

// ---------------- decoder init --------------------------------------------
__global__ void k_dec_init() {
    int b = blockIdx.x, k = threadIdx.x;
    int fpar = Sz & 1;   // 0
    g_hd[0][b*HDz + k] = (k < HEz) ? g_h[0][fpar][b*HEz + k]
                                   : g_h[1][fpar][b*HEz + (k - HEz)];
    if (k == 0) g_inp[b] = 2;  // SOS
}

// ---------------- q = Wattn @ [emb, h] + battn ----------------------------
// grid 128, block (32,4), dynamic smem 32*820*4
__global__ void k_attn_q(const float* __restrict__ emb_dec, const float* __restrict__ Wattn,
                         const float* __restrict__ battn, int par) {
    extern __shared__ float xs[];
    const int LD = 820;
    int b = threadIdx.x;
    int j = blockIdx.x * 4 + threadIdx.y;
    int tid = threadIdx.y*32 + threadIdx.x;
    for (int i = tid; i < Bz*XAz; i += 128) {
        int bb_ = i / XAz, c = i % XAz;
        float v = (c < Ez) ? emb_dec[(long)g_inp[bb_]*Ez + c]
                           : g_hd[par][bb_*HDz + (c - Ez)];
        xs[bb_*LD + c] = v;
    }
    __syncthreads();
    const float4* w4 = (const float4*)(Wattn + (long)j * XAz);
    const float4* x4 = (const float4*)(xs + b*LD);
    float a0 = battn[j], a1 = 0.f;
    #pragma unroll 4
    for (int c = 0; c < 202; c += 2) {
        float4 w = w4[c],   x = x4[c];
        a0 = fmaf(w.x,x.x,a0); a0 = fmaf(w.y,x.y,a0); a0 = fmaf(w.z,x.z,a0); a0 = fmaf(w.w,x.w,a0);
        float4 w2 = w4[c+1], x2 = x4[c+1];
        a1 = fmaf(w2.x,x2.x,a1); a1 = fmaf(w2.y,x2.y,a1); a1 = fmaf(w2.z,x2.z,a1); a1 = fmaf(w2.w,x2.w,a1);
    }
    { float4 w = w4[202], x = x4[202];
      a0 = fmaf(w.x,x.x,a0); a0 = fmaf(w.y,x.y,a0); a0 = fmaf(w.z,x.z,a0); a0 = fmaf(w.w,x.w,a0); }
    g_q[b*2*HEz + j] = a0 + a1;
}

// ---------------- attention scores + softmax + ctx ------------------------
__global__ void k_attn_ctx(float* __restrict__ out_att, int t) {
    int b = blockIdx.x, tid = threadIdx.x;
    __shared__ float qs[2*HEz];
    __shared__ float sc[Sz];
    __shared__ float red;
    qs[tid]       = g_q[b*2*HEz + tid];
    qs[tid + 256] = g_q[b*2*HEz + tid + 256];
    if (tid == 0) { g_amax[b] = 0ull; g_esum[b] = 0.f; }  // reset for this step
    __syncthreads();
    if (tid < Sz) {
        const float* enc = g_enc + ((long)b*Sz + tid)*2*HEz;
        float a = 0.f;
        #pragma unroll 4
        for (int c = 0; c < 2*HEz; c++) a = fmaf(qs[c], enc[c], a);
        sc[tid] = a;
    }
    __syncthreads();
    if (tid == 0) {
        float m = sc[0];
        for (int i = 1; i < Sz; i++) m = fmaxf(m, sc[i]);
        red = m;
    }
    __syncthreads();
    if (tid < Sz) sc[tid] = expf(sc[tid] - red);
    __syncthreads();
    if (tid == 0) {
        float ssum = 0.f;
        for (int i = 0; i < Sz; i++) ssum += sc[i];
        red = 1.f / ssum;
    }
    __syncthreads();
    if (tid < Sz) {
        sc[tid] *= red;
        out_att[((long)b*Tz + t)*Sz + tid] = sc[tid];
    }
    __syncthreads();
    for (int c = tid; c < 2*HEz; c += 256) {
        float a = 0.f;
        for (int s2 = 0; s2 < Sz; s2++)
            a = fmaf(sc[s2], g_enc[((long)b*Sz + s2)*2*HEz + c], a);
        g_ctx[b*2*HEz + c] = a;
    }
}

// ---------------- decoder GRU cell ----------------------------------------
// grid 128, block (32,4), dynamic smem 32*1332*4
__global__ void k_dec_gru(const float* __restrict__ emb_dec, const float* __restrict__ Wihd,
                          const float* __restrict__ Whhd, const float* __restrict__ bihd,
                          const float* __restrict__ bhhd, int par) {
    extern __shared__ float xs[];
    const int LD = 1332;
    int b = threadIdx.x;
    int k = blockIdx.x * 4 + threadIdx.y;
    int tid = threadIdx.y*32 + threadIdx.x;
    for (int i = tid; i < Bz*XTz; i += 128) {
        int bb_ = i / XTz, c = i % XTz;
        float v;
        if (c < Ez)        v = emb_dec[(long)g_inp[bb_]*Ez + c];
        else if (c < XAz)  v = g_ctx[bb_*2*HEz + (c - Ez)];
        else               v = g_hd[par][bb_*HDz + (c - XAz)];
        xs[bb_*LD + c] = v;
    }
    __syncthreads();
    float ar  = bihd[k] + bhhd[k];
    float az  = bihd[k + HDz] + bhhd[k + HDz];
    float ani = bihd[k + 2*HDz];
    float anh = bhhd[k + 2*HDz];
    const float4* wr = (const float4*)(Wihd + (long)k*XAz);
    const float4* wz = (const float4*)(Wihd + (long)(k + HDz)*XAz);
    const float4* wn = (const float4*)(Wihd + (long)(k + 2*HDz)*XAz);
    const float4* x4 = (const float4*)(xs + b*LD);
    #pragma unroll 4
    for (int c = 0; c < 203; c++) {
        float4 xv = x4[c];
        float4 a = wr[c], bq = wz[c], d = wn[c];
        ar  = fmaf(a.x,xv.x,ar);  ar  = fmaf(a.y,xv.y,ar);  ar  = fmaf(a.z,xv.z,ar);  ar  = fmaf(a.w,xv.w,ar);
        az  = fmaf(bq.x,xv.x,az); az  = fmaf(bq.y,xv.y,az); az  = fmaf(bq.z,xv.z,az); az  = fmaf(bq.w,xv.w,az);
        ani = fmaf(d.x,xv.x,ani); ani = fmaf(d.y,xv.y,ani); ani = fmaf(d.z,xv.z,ani); ani = fmaf(d.w,xv.w,ani);
    }
    const float4* hr = (const float4*)(Whhd + (long)k*HDz);
    const float4* hz = (const float4*)(Whhd + (long)(k + HDz)*HDz);
    const float4* hn = (const float4*)(Whhd + (long)(k + 2*HDz)*HDz);
    const float4* xh = (const float4*)(xs + b*LD + XAz);
    #pragma unroll 4
    for (int c = 0; c < 128; c++) {
        float4 hv = xh[c];
        float4 a = hr[c], bq = hz[c], d = hn[c];
        ar  = fmaf(a.x,hv.x,ar);  ar  = fmaf(a.y,hv.y,ar);  ar  = fmaf(a.z,hv.z,ar);  ar  = fmaf(a.w,hv.w,ar);
        az  = fmaf(bq.x,hv.x,az); az  = fmaf(bq.y,hv.y,az); az  = fmaf(bq.z,hv.z,az); az  = fmaf(bq.w,hv.w,az);
        anh = fmaf(d.x,hv.x,anh); anh = fmaf(d.y,hv.y,anh); anh = fmaf(d.z,hv.z,anh); anh = fmaf(d.w,hv.w,anh);
    }
    float r = sigm(ar), z = sigm(az);
    float n = tanhf(ani + r * anh);
    float hp = xs[b*LD + XAz + k];
    g_hd[par ^ 1][b*HDz + k] = (1.f - z) * n + z * hp;
}

// ---------------- output projection: all 32 batches per Wout read ---------
// C[v,b] = Wout[v,:] . h[b,:] + bout[v].  lane = batch, warp = K-slice of 64.
// W tiles of 8 rows double-buffered via cp.async; FFMA2 inner product.
// grid 146, block 256, dynamic smem 86624 B.
__global__ __launch_bounds__(256) void k_out_gemm(
        const float* __restrict__ Wout, const float* __restrict__ bout,
        float* __restrict__ out_logp, int t, int par) {
    extern __shared__ float sm[];
    float* wt  = sm;                    // [2][8*512]
    float* sl  = sm + 8192;             // [344][33]
    float* red = sm + 8192 + OG_ROWS*33;// [8][8][33]

    int tid  = threadIdx.x;
    int ws   = tid >> 5;
    int lane = tid & 31;
    int v0   = blockIdx.x * OG_ROWS;

    // h slice for this lane's batch, this warp's K range, in registers
    ulonglong2 hx[16];
    {
        const ulonglong2* hb = (const ulonglong2*)(g_hd[par ^ 1] + lane*HDz + ws*64);
        #pragma unroll
        for (int j = 0; j < 16; j++) hx[j] = hb[j];
    }

    unsigned int wt_s = (unsigned int)__cvta_generic_to_shared(wt);

    // stage group g into buffer buf
    auto stage = [&](int buf, int g) {
        int vbase = v0 + g*8;
        #pragma unroll
        for (int q = 0; q < 4; q++) {
            int f = tid + 256*q;                 // [0,1024) float4s
            int r = f >> 7, c4 = f & 127;
            int v = vbase + r; if (v > VDz-1) v = VDz-1;
            cpa16(wt_s + (unsigned)(buf*4096 + f*4)*4u,
                  Wout + (long)v*HDz + c4*4);
        }
        asm volatile("cp.async.commit_group;");
    };

    stage(0, 0);

    for (int g = 0; g < OG_NGRP; g++) {
        int buf = g & 1;
        if (g + 1 < OG_NGRP) {
            stage(buf ^ 1, g + 1);
            asm volatile("cp.async.wait_group 1;");
        } else {
            asm volatile("cp.async.wait_group 0;");
        }
        __syncthreads();

        unsigned long long acc[8];
        #pragma unroll
        for (int r = 0; r < 8; r++) acc[r] = 0ull;
        const ulonglong2* wbase = (const ulonglong2*)(wt + buf*4096 + ws*64);
        #pragma unroll
        for (int j4 = 0; j4 < 16; j4++) {
            ulonglong2 h2 = hx[j4];
            #pragma unroll
            for (int r = 0; r < 8; r++) {
                ulonglong2 w = wbase[r*128 + j4];     // uniform LDS.128
                acc[r] = ffma2(w.x, h2.x, acc[r]);
                acc[r] = ffma2(w.y, h2.y, acc[r]);
            }
        }
        #pragma unroll
        for (int r = 0; r < 8; r++) {
            float lo = __uint_as_float((unsigned)(acc[r] & 0xffffffffull));
            float hi = __uint_as_float((unsigned)(acc[r] >> 32));
            red[r*264 + ws*33 + lane] = lo + hi;
        }
        __syncthreads();
        {   // warp ws reduces row ws of this group
            int r = ws;
            float s = red[r*264 + 0*33 + lane] + red[r*264 + 1*33 + lane]
                    + red[r*264 + 2*33 + lane] + red[r*264 + 3*33 + lane]
                    + red[r*264 + 4*33 + lane] + red[r*264 + 5*33 + lane]
                    + red[r*264 + 6*33 + lane] + red[r*264 + 7*33 + lane];
            int v = v0 + g*8 + r;
            if (v < VDz) s += bout[v];
            sl[(g*8 + r)*33 + lane] = s;
        }
        __syncthreads();
    }

    // epilogue: each warp handles 4 batches; coalesced store + exp-sum + argmax
    float* outb = out_logp;
    #pragma unroll
    for (int sub = 0; sub < 4; sub++) {
        int b = ws*4 + sub;
        float esum = 0.f;
        unsigned long long pk = 0ull;
        float* dst = outb + ((long)(b*Tz + t))*VDz + v0;
        #pragma unroll
        for (int j = 0; j < 11; j++) {
            int vv = lane + 32*j;
            if (vv < OG_ROWS && v0 + vv < VDz) {
                float lg = sl[vv*33 + b];
                dst[vv] = lg;
                esum += expf(lg);
                unsigned u = __float_as_uint(lg);
                u = (u & 0x80000000u) ? ~u : (u | 0x80000000u);
                unsigned long long p = ((unsigned long long)u << 32)
                                     | (unsigned long long)(0xFFFFFFFFu - (unsigned)(v0 + vv));
                pk = (p > pk) ? p : pk;
            }
        }
        #pragma unroll
        for (int off = 16; off > 0; off >>= 1) {
            esum += __shfl_xor_sync(0xffffffffu, esum, off);
            unsigned long long o =
                (((unsigned long long)__shfl_xor_sync(0xffffffffu, (unsigned)(pk >> 32), off)) << 32)
                | (unsigned long long)__shfl_xor_sync(0xffffffffu, (unsigned)(pk & 0xffffffffull), off);
            pk = (o > pk) ? o : pk;
        }
        if (lane == 0) {
            atomicAdd(&g_esum[b], esum);
            atomicMax(&g_amax[b], pk);
        }
    }
}

// ---------------- per-step finalize ---------------------------------------
__global__ void k_finalize_step(int t) {
    int b = threadIdx.x;
    if (b < Bz) {
        g_logZ[t*Bz + b] = logf(g_esum[b]);
        unsigned vv = 0xFFFFFFFFu - (unsigned)(g_amax[b] & 0xFFFFFFFFull);
        g_inp[b] = (int)vv;
        g_idx[b*Tz + t] = (int)vv;
    }
}

// ---------------- EOS mask + idx as float ---------------------------------
__global__ void k_mask(float* __restrict__ out_idx, float* __restrict__ out_mask) {
    int b = threadIdx.x;
    if (b >= Bz) return;
    int cnt = 0;
    for (int t = 0; t < Tz; t++) {
        int v = g_idx[b*Tz + t];
        cnt += (v == 3);
        out_idx[b*Tz + t]  = (float)v;
        out_mask[b*Tz + t] = (cnt == 0) ? 1.f : 0.f;
    }
}

// ---------------- final log-softmax normalization -------------------------
__global__ void k_logp_final(float* __restrict__ out_logp) {
    long i4 = (long)blockIdx.x * 256 + threadIdx.x;
    long e0 = i4 * 4;
    int bt = (int)(e0 / VDz);
    int b = bt / Tz, t = bt % Tz;
    float lz = g_logZ[t*Bz + b];
    float4* p = (float4*)out_logp + i4;
    float4 v = *p;
    v.x -= lz; v.y -= lz; v.z -= lz; v.w -= lz;
    *p = v;
}

// =========================================================================
extern "C" void kernel_launch(void* const* d_in, const int* in_sizes, int n_in,
                              void* d_out, int out_size) {
    const int*   data    = (const int*)  d_in[0];
    const float* emb_enc = (const float*)d_in[4];
    const float* emb_dec = (const float*)d_in[5];
    const float* Wihf = (const float*)d_in[6],  *Whhf = (const float*)d_in[7];
    const float* bihf = (const float*)d_in[8],  *bhhf = (const float*)d_in[9];
    const float* Wihb = (const float*)d_in[10], *Whhb = (const float*)d_in[11];
    const float* bihb = (const float*)d_in[12], *bhhb = (const float*)d_in[13];
    const float* Wihd = (const float*)d_in[14], *Whhd = (const float*)d_in[15];
    const float* bihd = (const float*)d_in[16], *bhhd = (const float*)d_in[17];
    const float* Wattn = (const float*)d_in[18], *battn = (const float*)d_in[19];
    const float* Wout  = (const float*)d_in[20], *bout  = (const float*)d_in[21];

    float* out      = (float*)d_out;
    float* out_logp = out;                                   // [B,T,VD]
    float* out_idx  = out + (long)Bz*Tz*VDz;                 // [B,T]
    float* out_mask = out_idx + Bz*Tz;                       // [B,T]
    float* out_att  = out_mask + Bz*Tz;                      // [B,T,S]

    const int smemQ = Bz * 820 * 4;                          // 104,960 B
    const int smemG = Bz * 1332 * 4;                         // 170,496 B
    const int smemO = (8192 + OG_ROWS*33 + 8*8*33) * 4;      // 86,624 B
    cudaFuncSetAttribute(k_attn_q,   cudaFuncAttributeMaxDynamicSharedMemorySize, smemQ);
    cudaFuncSetAttribute(k_dec_gru,  cudaFuncAttributeMaxDynamicSharedMemorySize, smemG);
    cudaFuncSetAttribute(k_out_gemm, cudaFuncAttributeMaxDynamicSharedMemorySize, smemO);

    // ---- encoder ----
    k_zero<<<(Bz*HEz + 255)/256, 256>>>();
    k_embed_enc<<<(Sz*Bz*Ez + 255)/256, 256>>>(data, emb_enc);
    k_gi<<<dim3(96, Sz, 2), dim3(32, 8)>>>(Wihf, bihf, Wihb, bihb);
    for (int s = 0; s < Sz; s++)
        k_enc_step<<<dim3(64, 2), dim3(32, 4)>>>(s, Whhf, bhhf, Whhb, bhhb);
    k_dec_init<<<Bz, HDz>>>();

    // ---- decoder (greedy, argmax feedback) ----
    for (int t = 0; t < Tz; t++) {
        int par = t & 1;
        k_attn_q<<<128, dim3(32, 4), smemQ>>>(emb_dec, Wattn, battn, par);
        k_attn_ctx<<<Bz, 256>>>(out_att, t);
        k_dec_gru<<<128, dim3(32, 4), smemG>>>(emb_dec, Wihd, Whhd, bihd, bhhd, par);
        k_out_gemm<<<OG_GRID, 256, smemO>>>(Wout, bout, out_logp, t, par);
        k_finalize_step<<<1, 32>>>(t);
    }

    // ---- finalize outputs ----
    k_mask<<<1, 32>>>(out_idx, out_mask);
    k_logp_final<<<(int)(((long)Bz*Tz*VDz/4 + 255)/256), 256>>>(out_logp);
}

// round 11
// speedup vs baseline: 3.0223x; 2.0741x over previous
#include <cuda_runtime.h>
#include <cuda_bf16.h>
#include <math.h>

#define Bz 32
#define Sz 64
#define Tz 32
#define Ez 300
#define HEz 256
#define HDz 512
#define VDz 50000

#define OG_ROWS 344
#define OG_NGRP 43
#define DEC_BLKS 146

// ---------------- device scratch (static, no allocation) ----------------
__device__ __align__(16) float g_X[Sz*Bz*Ez];
__device__ __align__(16) float g_GI[2][Sz*Bz*3*HEz];
__device__ __align__(16) float g_hT[2][2][HEz*Bz];    // [dir][parity][u*32+b]
__device__ __align__(16) float g_enc[Bz*Sz*2*HEz];    // [b][s][c]
__device__ __align__(16) float g_hd[2][Bz*HDz];       // decoder hidden ping-pong
__device__ __align__(16) float g_q[Bz*HDz];           // [b][j]
__device__ __align__(16) float g_ctx[Bz*2*HEz];
__device__ int   g_inp[Bz];
__device__ int   g_idx[Bz*Tz];
__device__ unsigned long long g_amax[Bz];
__device__ float g_esum[Bz];
__device__ float g_logZ[Tz*Bz];
__device__ int           g_cnt[4];
__device__ volatile int  g_ep[4];

__device__ __forceinline__ float sigm(float x) { return 1.f / (1.f + expf(-x)); }

__device__ __forceinline__ unsigned long long ffma2(unsigned long long a,
                                                    unsigned long long b,
                                                    unsigned long long c) {
    unsigned long long d;
    asm("fma.rn.f32x2 %0, %1, %2, %3;" : "=l"(d) : "l"(a), "l"(b), "l"(c));
    return d;
}

__device__ __forceinline__ void cpa16(unsigned int dst, const void* src) {
    asm volatile("cp.async.cg.shared.global [%0], [%1], 16;" :: "r"(dst), "l"(src));
}

// grid barrier over n co-resident blocks (epoch/counter; graph-safe)
__device__ __forceinline__ void gbar(int id, int n) {
    __syncthreads();
    if (threadIdx.x == 0) {
        __threadfence();
        int e = g_ep[id];
        if (atomicAdd(&g_cnt[id], 1) == n - 1) {
            atomicExch(&g_cnt[id], 0);
            __threadfence();
            g_ep[id] = e + 1;
        } else {
            while (g_ep[id] == e) { }
            __threadfence();
        }
    }
    __syncthreads();
}

// ---------------- encoder embedding gather --------------------------------
__global__ void k_embed_enc(const int* __restrict__ data, const float* __restrict__ emb) {
    int i = blockIdx.x * 256 + threadIdx.x;
    if (i >= Sz*Bz*Ez) return;
    int e = i % Ez; int sb = i / Ez; int b = sb % Bz; int s = sb / Bz;
    g_X[i] = emb[(long)data[b*Sz + s]*Ez + e];
}

// ---------------- batched input-gate GEMM, both directions ----------------
__global__ void k_gi(const float* __restrict__ Wf, const float* __restrict__ bf,
                     const float* __restrict__ Wb, const float* __restrict__ bb) {
    int s = blockIdx.y, dir = blockIdx.z;
    int b = threadIdx.x;
    int j = blockIdx.x * 8 + threadIdx.y;
    __shared__ float xs[Bz][308];
    int tid = threadIdx.y*32 + threadIdx.x;
    for (int i = tid; i < Bz*75; i += 256) {
        int b_ = i / 75, c4 = i % 75;
        *(float4*)&xs[b_][c4*4] = *(const float4*)&g_X[((long)s*Bz + b_)*Ez + c4*4];
    }
    __syncthreads();
    const float* W  = dir ? Wb : Wf;
    const float* bi = dir ? bb : bf;
    const float4* w4 = (const float4*)(W + (long)j * Ez);
    const float4* x4 = (const float4*)&xs[b][0];
    float a0 = bi[j], a1 = 0.f;
    #pragma unroll 4
    for (int c = 0; c < 74; c += 2) {
        float4 w = w4[c],   x = x4[c];
        a0 = fmaf(w.x,x.x,a0); a0 = fmaf(w.y,x.y,a0); a0 = fmaf(w.z,x.z,a0); a0 = fmaf(w.w,x.w,a0);
        float4 w2 = w4[c+1], x2 = x4[c+1];
        a1 = fmaf(w2.x,x2.x,a1); a1 = fmaf(w2.y,x2.y,a1); a1 = fmaf(w2.z,x2.z,a1); a1 = fmaf(w2.w,x2.w,a1);
    }
    { float4 w = w4[74], x = x4[74];
      a0 = fmaf(w.x,x.x,a0); a0 = fmaf(w.y,x.y,a0); a0 = fmaf(w.z,x.z,a0); a0 = fmaf(w.w,x.w,a0); }
    int sd = dir ? (Sz - 1 - s) : s;
    g_GI[dir][((long)sd*Bz + b)*3*HEz + j] = a0 + a1;
}

// ---------------- persistent bidirectional encoder ------------------------
// grid 64 (dir = bid>>5, ublk = bid&31), block 256 (lane=b, warp=y; u = ublk*8+y)
// smem: ws[8][768] weights staged once + hsT[256][33] transposed h
__global__ __launch_bounds__(256, 1) void k_enc_all(
        const float* __restrict__ Whhf, const float* __restrict__ bhhf,
        const float* __restrict__ Whhb, const float* __restrict__ bhhb) {
    extern __shared__ float sm[];
    float* wsm = sm;            // 8*768
    float* hsT = sm + 8*768;    // 256*33
    int tid = threadIdx.x;
    int b = tid & 31, y = tid >> 5;
    int bid = blockIdx.x;
    int dir = bid >> 5, ublk = bid & 31;
    int u0 = ublk * 8;
    int u  = u0 + y;

    const float* Whh = dir ? Whhb : Whhf;
    const float* bhh = dir ? bhhb : bhhf;

    // stage weights once
    for (int i = tid; i < 8*768; i += 256) {
        int yy = i / 768, rem = i % 768;
        int g = rem >> 8, c = rem & 255;
        wsm[i] = Whh[((long)(g*HEz + u0 + yy))*HEz + c];
    }
    // zero h staging (h0 = 0)
    for (int i = tid; i < 256*33; i += 256) hsT[i] = 0.f;
    // decoder-shared init
    if (bid == 0 && tid < Bz) {
        g_inp[tid] = 2;             // SOS
        g_esum[tid] = 0.f;
        g_amax[tid] = 0ull;
    }

    float br_ = bhh[u], bz_ = bhh[u + HEz], bn_ = bhh[u + 2*HEz];
    const float4* wr4 = (const float4*)(wsm + y*768);
    const float4* wz4 = (const float4*)(wsm + y*768 + 256);
    const float4* wn4 = (const float4*)(wsm + y*768 + 512);
    const float* GIb = g_GI[dir];

    #pragma unroll 1
    for (int s = 0; s < Sz; s++) {
        int par = s & 1;
        if (s > 0) {
            const float4* src = (const float4*)(g_hT[dir][par]);
            #pragma unroll
            for (int k = 0; k < 8; k++) {
                int i4 = tid + k*256;
                float4 v = src[i4];
                int c = i4 >> 3, b4 = (i4 & 7) * 4;
                int cb = c*33 + b4;
                hsT[cb] = v.x; hsT[cb+1] = v.y; hsT[cb+2] = v.z; hsT[cb+3] = v.w;
            }
        }
        const float* GI = GIb + ((long)s*Bz + b)*3*HEz + u;
        float gr = GI[0], gz = GI[HEz], gn = GI[2*HEz];
        __syncthreads();

        float ar = gr + br_, az = gz + bz_, an = bn_;
        #pragma unroll 4
        for (int c4 = 0; c4 < 64; c4++) {
            int cb = (c4<<2)*33 + b;
            float h0 = hsT[cb], h1 = hsT[cb+33], h2 = hsT[cb+66], h3 = hsT[cb+99];
            float4 w = wr4[c4];
            ar = fmaf(w.x,h0,fmaf(w.y,h1,fmaf(w.z,h2,fmaf(w.w,h3,ar))));
            w = wz4[c4];
            az = fmaf(w.x,h0,fmaf(w.y,h1,fmaf(w.z,h2,fmaf(w.w,h3,az))));
            w = wn4[c4];
            an = fmaf(w.x,h0,fmaf(w.y,h1,fmaf(w.z,h2,fmaf(w.w,h3,an))));
        }
        float r = sigm(ar), z = sigm(az);
        float n = tanhf(gn + r * an);
        float hp = hsT[u*33 + b];
        float hn = (1.f - z) * n + z * hp;

        g_hT[dir][par ^ 1][u*Bz + b] = hn;                 // coalesced
        int sd = dir ? (Sz - 1 - s) : s;
        g_enc[((long)b*Sz + sd)*2*HEz + dir*HEz + u] = hn; // scatter
        if (s == Sz-1) g_hd[0][b*HDz + dir*HEz + u] = hn;  // decoder h0
        gbar(dir, 32);
    }
}

// ---------------- persistent decoder (whole greedy loop) ------------------
// grid 146, block 256.  dyn smem: xT[1324][33] (P1/P3) overlaid by P4 region.
__global__ __launch_bounds__(256, 1) void k_dec_all(
        const float* __restrict__ emb_dec,
        const float* __restrict__ Wattn, const float* __restrict__ battn,
        const float* __restrict__ Wihd,  const float* __restrict__ Whhd,
        const float* __restrict__ bihd,  const float* __restrict__ bhhd,
        const float* __restrict__ Wout,  const float* __restrict__ bout,
        float* __restrict__ out_logp, float* __restrict__ out_att) {
    extern __shared__ float sm[];
    __shared__ float s_q[HDz];
    __shared__ float s_sc[Sz];
    __shared__ float s_red[1024];   // P1: [8][32]; P3: [8][4][32]
    __shared__ float s_r1;

    float* xT = sm;                          // 1324*33 floats
    int tid = threadIdx.x;
    int w = tid >> 5, lane = tid & 31;
    int gid = blockIdx.x;
    int r = w & 3, half = w >> 2;

    #pragma unroll 1
    for (int t = 0; t < Tz; t++) {
        int par = t & 1;

        // ======== P1: q = Wattn @ [emb, h] + battn ========
        if (gid < 128) {
            // fill xT: emb [0,300), h [300,812)
            for (int i = tid; i < Bz*75; i += 256) {
                int b = i / 75, c4 = i % 75;
                float4 v = *(const float4*)(emb_dec + (long)g_inp[b]*Ez + (c4<<2));
                int cb = (c4<<2)*33 + b;
                xT[cb] = v.x; xT[cb+33] = v.y; xT[cb+66] = v.z; xT[cb+99] = v.w;
            }
            for (int i = tid; i < Bz*128; i += 256) {
                int b = i >> 7, c4 = i & 127;
                float4 v = *(const float4*)(g_hd[par] + b*HDz + (c4<<2));
                int cb = (300 + (c4<<2))*33 + b;
                xT[cb] = v.x; xT[cb+33] = v.y; xT[cb+66] = v.z; xT[cb+99] = v.w;
            }
            __syncthreads();
            {
                int j = (gid<<2) + r;
                const float4* w4 = (const float4*)(Wattn + (long)j*812);
                int c40 = half*102, c41 = half ? 203 : 102;
                float acc = 0.f;
                #pragma unroll 4
                for (int c4 = c40; c4 < c41; c4++) {
                    float4 wv = w4[c4];
                    int cb = (c4<<2)*33 + lane;
                    acc = fmaf(wv.x, xT[cb],    acc);
                    acc = fmaf(wv.y, xT[cb+33], acc);
                    acc = fmaf(wv.z, xT[cb+66], acc);
                    acc = fmaf(wv.w, xT[cb+99], acc);
                }
                s_red[w*32 + lane] = acc;
            }
            __syncthreads();
            if (w < 4) {
                float qv = s_red[w*32 + lane] + s_red[(w+4)*32 + lane] + battn[(gid<<2) + w];
                g_q[lane*HDz + (gid<<2) + w] = qv;
            }
        }
        gbar(2, DEC_BLKS);

        // ======== P2: scores + softmax + ctx (blocks 0..31, b = gid) ======
        if (gid < Bz) {
            int b = gid;
            for (int i = tid; i < HDz; i += 256) s_q[i] = g_q[b*HDz + i];
            __syncthreads();
            {
                const float4* q4 = (const float4*)s_q;
                #pragma unroll
                for (int k = 0; k < 8; k++) {
                    int s2 = w*8 + k;
                    const float4* e4 = (const float4*)(g_enc + ((long)b*Sz + s2)*2*HEz);
                    float a = 0.f;
                    #pragma unroll
                    for (int c4 = lane; c4 < 128; c4 += 32) {
                        float4 e = e4[c4], q = q4[c4];
                        a = fmaf(e.x,q.x,a); a = fmaf(e.y,q.y,a);
                        a = fmaf(e.z,q.z,a); a = fmaf(e.w,q.w,a);
                    }
                    a += __shfl_xor_sync(0xffffffffu, a, 16);
                    a += __shfl_xor_sync(0xffffffffu, a, 8);
                    a += __shfl_xor_sync(0xffffffffu, a, 4);
                    a += __shfl_xor_sync(0xffffffffu, a, 2);
                    a += __shfl_xor_sync(0xffffffffu, a, 1);
                    if (lane == 0) s_sc[s2] = a;
                }
            }
            __syncthreads();
            if (tid == 0) {
                float m = s_sc[0];
                for (int i = 1; i < Sz; i++) m = fmaxf(m, s_sc[i]);
                s_r1 = m;
            }
            __syncthreads();
            if (tid < Sz) s_sc[tid] = expf(s_sc[tid] - s_r1);
            __syncthreads();
            if (tid == 0) {
                float ss = 0.f;
                for (int i = 0; i < Sz; i++) ss += s_sc[i];
                s_r1 = 1.f / ss;
            }
            __syncthreads();
            if (tid < Sz) {
                s_sc[tid] *= s_r1;
                out_att[((long)b*Tz + t)*Sz + tid] = s_sc[tid];
            }
            __syncthreads();
            #pragma unroll
            for (int h2 = 0; h2 < 2; h2++) {
                int c = tid + h2*256;
                float a = 0.f;
                for (int s2 = 0; s2 < Sz; s2++)
                    a = fmaf(s_sc[s2], g_enc[((long)b*Sz + s2)*2*HEz + c], a);
                g_ctx[b*2*HEz + c] = a;
            }
        }
        gbar(2, DEC_BLKS);

        // ======== P3: GRU cell ========
        if (gid < 128) {
            // fill ctx [300,812), h [812,1324)  (emb part persists from P1)
            for (int i = tid; i < Bz*128; i += 256) {
                int b = i >> 7, c4 = i & 127;
                float4 v = *(const float4*)(g_ctx + b*2*HEz + (c4<<2));
                int cb = (300 + (c4<<2))*33 + b;
                xT[cb] = v.x; xT[cb+33] = v.y; xT[cb+66] = v.z; xT[cb+99] = v.w;
            }
            for (int i = tid; i < Bz*128; i += 256) {
                int b = i >> 7, c4 = i & 127;
                float4 v = *(const float4*)(g_hd[par] + b*HDz + (c4<<2));
                int cb = (812 + (c4<<2))*33 + b;
                xT[cb] = v.x; xT[cb+33] = v.y; xT[cb+66] = v.z; xT[cb+99] = v.w;
            }
            __syncthreads();
            {
                int R = (gid<<2) + r;
                const float4* wr4 = (const float4*)(Wihd + (long)R*812);
                const float4* wz4 = (const float4*)(Wihd + (long)(HDz + R)*812);
                const float4* wn4 = (const float4*)(Wihd + (long)(2*HDz + R)*812);
                float ar = 0.f, az = 0.f, ani = 0.f, anh = 0.f;
                int c40 = half*102, c41 = half ? 203 : 102;
                #pragma unroll 2
                for (int c4 = c40; c4 < c41; c4++) {
                    int cb = (c4<<2)*33 + lane;
                    float x0 = xT[cb], x1 = xT[cb+33], x2 = xT[cb+66], x3 = xT[cb+99];
                    float4 wv = wr4[c4];
                    ar = fmaf(wv.x,x0,fmaf(wv.y,x1,fmaf(wv.z,x2,fmaf(wv.w,x3,ar))));
                    wv = wz4[c4];
                    az = fmaf(wv.x,x0,fmaf(wv.y,x1,fmaf(wv.z,x2,fmaf(wv.w,x3,az))));
                    wv = wn4[c4];
                    ani = fmaf(wv.x,x0,fmaf(wv.y,x1,fmaf(wv.z,x2,fmaf(wv.w,x3,ani))));
                }
                const float4* hr4 = (const float4*)(Whhd + (long)R*HDz);
                const float4* hz4 = (const float4*)(Whhd + (long)(HDz + R)*HDz);
                const float4* hn4 = (const float4*)(Whhd + (long)(2*HDz + R)*HDz);
                int d40 = half*64, d41 = half ? 128 : 64;
                #pragma unroll 2
                for (int c4 = d40; c4 < d41; c4++) {
                    int cb = (812 + (c4<<2))*33 + lane;
                    float x0 = xT[cb], x1 = xT[cb+33], x2 = xT[cb+66], x3 = xT[cb+99];
                    float4 wv = hr4[c4];
                    ar = fmaf(wv.x,x0,fmaf(wv.y,x1,fmaf(wv.z,x2,fmaf(wv.w,x3,ar))));
                    wv = hz4[c4];
                    az = fmaf(wv.x,x0,fmaf(wv.y,x1,fmaf(wv.z,x2,fmaf(wv.w,x3,az))));
                    wv = hn4[c4];
                    anh = fmaf(wv.x,x0,fmaf(wv.y,x1,fmaf(wv.z,x2,fmaf(wv.w,x3,anh))));
                }
                s_red[(w<<7) +      lane] = ar;
                s_red[(w<<7) + 32 + lane] = az;
                s_red[(w<<7) + 64 + lane] = ani;
                s_red[(w<<7) + 96 + lane] = anh;
            }
            __syncthreads();
            if (w < 4) {
                int R2 = (gid<<2) + w;
                float ar  = s_red[(w<<7)+lane]    + s_red[((w+4)<<7)+lane]    + bihd[R2] + bhhd[R2];
                float az  = s_red[(w<<7)+32+lane] + s_red[((w+4)<<7)+32+lane] + bihd[R2+HDz] + bhhd[R2+HDz];
                float ani = s_red[(w<<7)+64+lane] + s_red[((w+4)<<7)+64+lane] + bihd[R2+2*HDz];
                float anh = s_red[(w<<7)+96+lane] + s_red[((w+4)<<7)+96+lane] + bhhd[R2+2*HDz];
                float rr = sigm(ar), z = sigm(az);
                float n = tanhf(ani + rr * anh);
                float hp = g_hd[par][lane*HDz + R2];
                g_hd[par ^ 1][lane*HDz + R2] = (1.f - z) * n + z * hp;
            }
        }
        gbar(2, DEC_BLKS);

        // ======== P4: output projection (all 146 blocks) ========
        {
            float* wt   = sm;                          // [2][8*512]
            float* sl   = sm + 8192;                   // [344][33]
            float* red4 = sm + 8192 + OG_ROWS*33;      // [8][8][33]
            int v0 = gid * OG_ROWS;

            ulonglong2 hx[16];
            {
                const ulonglong2* hb = (const ulonglong2*)(g_hd[par ^ 1] + lane*HDz + w*64);
                #pragma unroll
                for (int j = 0; j < 16; j++) hx[j] = hb[j];
            }
            unsigned int wt_s = (unsigned int)__cvta_generic_to_shared(wt);
            __syncthreads();   // xT dead, safe to overlay

            auto stage = [&](int buf, int g) {
                int vbase = v0 + g*8;
                #pragma unroll
                for (int q = 0; q < 4; q++) {
                    int f = tid + 256*q;
                    int rr = f >> 7, c4 = f & 127;
                    int v = vbase + rr; if (v > VDz-1) v = VDz-1;
                    cpa16(wt_s + (unsigned)(buf*4096 + f*4)*4u,
                          Wout + (long)v*HDz + c4*4);
                }
                asm volatile("cp.async.commit_group;");
            };

            stage(0, 0);
            for (int g = 0; g < OG_NGRP; g++) {
                int buf = g & 1;
                if (g + 1 < OG_NGRP) {
                    stage(buf ^ 1, g + 1);
                    asm volatile("cp.async.wait_group 1;");
                } else {
                    asm volatile("cp.async.wait_group 0;");
                }
                __syncthreads();

                unsigned long long acc[8];
                #pragma unroll
                for (int rr = 0; rr < 8; rr++) acc[rr] = 0ull;
                const ulonglong2* wbase = (const ulonglong2*)(wt + buf*4096 + w*64);
                #pragma unroll
                for (int j4 = 0; j4 < 16; j4++) {
                    ulonglong2 h2 = hx[j4];
                    #pragma unroll
                    for (int rr = 0; rr < 8; rr++) {
                        ulonglong2 wv = wbase[rr*128 + j4];
                        acc[rr] = ffma2(wv.x, h2.x, acc[rr]);
                        acc[rr] = ffma2(wv.y, h2.y, acc[rr]);
                    }
                }
                #pragma unroll
                for (int rr = 0; rr < 8; rr++) {
                    float lo = __uint_as_float((unsigned)(acc[rr] & 0xffffffffull));
                    float hi = __uint_as_float((unsigned)(acc[rr] >> 32));
                    red4[rr*264 + w*33 + lane] = lo + hi;
                }
                __syncthreads();
                {
                    int rr = w;
                    float s = red4[rr*264 + 0*33 + lane] + red4[rr*264 + 1*33 + lane]
                            + red4[rr*264 + 2*33 + lane] + red4[rr*264 + 3*33 + lane]
                            + red4[rr*264 + 4*33 + lane] + red4[rr*264 + 5*33 + lane]
                            + red4[rr*264 + 6*33 + lane] + red4[rr*264 + 7*33 + lane];
                    int v = v0 + g*8 + rr;
                    if (v < VDz) s += bout[v];
                    sl[(g*8 + rr)*33 + lane] = s;
                }
                __syncthreads();
            }

            // epilogue: warp handles 4 batches
            #pragma unroll
            for (int sub = 0; sub < 4; sub++) {
                int b = w*4 + sub;
                float esum = 0.f;
                unsigned long long pk = 0ull;
                float* dst = out_logp + ((long)(b*Tz + t))*VDz + v0;
                #pragma unroll
                for (int j = 0; j < 11; j++) {
                    int vv = lane + 32*j;
                    if (vv < OG_ROWS && v0 + vv < VDz) {
                        float lg = sl[vv*33 + b];
                        dst[vv] = lg;
                        esum += expf(lg);
                        unsigned u = __float_as_uint(lg);
                        u = (u & 0x80000000u) ? ~u : (u | 0x80000000u);
                        unsigned long long p = ((unsigned long long)u << 32)
                                             | (unsigned long long)(0xFFFFFFFFu - (unsigned)(v0 + vv));
                        pk = (p > pk) ? p : pk;
                    }
                }
                #pragma unroll
                for (int off = 16; off > 0; off >>= 1) {
                    esum += __shfl_xor_sync(0xffffffffu, esum, off);
                    unsigned long long o =
                        (((unsigned long long)__shfl_xor_sync(0xffffffffu, (unsigned)(pk >> 32), off)) << 32)
                        | (unsigned long long)__shfl_xor_sync(0xffffffffu, (unsigned)(pk & 0xffffffffull), off);
                    pk = (o > pk) ? o : pk;
                }
                if (lane == 0) {
                    atomicAdd(&g_esum[b], esum);
                    atomicMax(&g_amax[b], pk);
                }
            }
        }

        // ======== barrier + last-block finalize ========
        __syncthreads();
        if (tid == 0) {
            __threadfence();
            int e = g_ep[2];
            if (atomicAdd(&g_cnt[2], 1) == DEC_BLKS - 1) {
                #pragma unroll 1
                for (int b = 0; b < Bz; b++) {
                    g_logZ[t*Bz + b] = logf(g_esum[b]);
                    unsigned vv = 0xFFFFFFFFu - (unsigned)(g_amax[b] & 0xFFFFFFFFull);
                    g_inp[b] = (int)vv;
                    g_idx[b*Tz + t] = (int)vv;
                    g_esum[b] = 0.f;
                    g_amax[b] = 0ull;
                }
                atomicExch(&g_cnt[2], 0);
                __threadfence();
                g_ep[2] = e + 1;
            } else {
                while (g_ep[2] == e) { }
                __threadfence();
            }
        }
        __syncthreads();
    }
}

// ---------------- EOS mask + idx as float ---------------------------------
__global__ void k_mask(float* __restrict__ out_idx, float* __restrict__ out_mask) {
    int b = threadIdx.x;
    if (b >= Bz) return;
    int cnt = 0;
    for (int t = 0; t < Tz; t++) {
        int v = g_idx[b*Tz + t];
        cnt += (v == 3);
        out_idx[b*Tz + t]  = (float)v;
        out_mask[b*Tz + t] = (cnt == 0) ? 1.f : 0.f;
    }
}

// ---------------- final log-softmax normalization -------------------------
__global__ void k_logp_final(float* __restrict__ out_logp) {
    long i4 = (long)blockIdx.x * 256 + threadIdx.x;
    long e0 = i4 * 4;
    int bt = (int)(e0 / VDz);
    int b = bt / Tz, t = bt % Tz;
    float lz = g_logZ[t*Bz + b];
    float4* p = (float4*)out_logp + i4;
    float4 v = *p;
    v.x -= lz; v.y -= lz; v.z -= lz; v.w -= lz;
    *p = v;
}

// =========================================================================
extern "C" void kernel_launch(void* const* d_in, const int* in_sizes, int n_in,
                              void* d_out, int out_size) {
    const int*   data    = (const int*)  d_in[0];
    const float* emb_enc = (const float*)d_in[4];
    const float* emb_dec = (const float*)d_in[5];
    const float* Wihf = (const float*)d_in[6],  *Whhf = (const float*)d_in[7];
    const float* bihf = (const float*)d_in[8],  *bhhf = (const float*)d_in[9];
    const float* Wihb = (const float*)d_in[10], *Whhb = (const float*)d_in[11];
    const float* bihb = (const float*)d_in[12], *bhhb = (const float*)d_in[13];
    const float* Wihd = (const float*)d_in[14], *Whhd = (const float*)d_in[15];
    const float* bihd = (const float*)d_in[16], *bhhd = (const float*)d_in[17];
    const float* Wattn = (const float*)d_in[18], *battn = (const float*)d_in[19];
    const float* Wout  = (const float*)d_in[20], *bout  = (const float*)d_in[21];

    float* out      = (float*)d_out;
    float* out_logp = out;                                   // [B,T,VD]
    float* out_idx  = out + (long)Bz*Tz*VDz;                 // [B,T]
    float* out_mask = out_idx + Bz*Tz;                       // [B,T]
    float* out_att  = out_mask + Bz*Tz;                      // [B,T,S]

    const int smemE = (8*768 + 256*33) * 4;                  // 58,368 B
    const int smemD = 1324 * 33 * 4;                         // 174,768 B
    cudaFuncSetAttribute(k_enc_all, cudaFuncAttributeMaxDynamicSharedMemorySize, smemE);
    cudaFuncSetAttribute(k_dec_all, cudaFuncAttributeMaxDynamicSharedMemorySize, smemD);

    k_embed_enc<<<(Sz*Bz*Ez + 255)/256, 256>>>(data, emb_enc);
    k_gi<<<dim3(96, Sz, 2), dim3(32, 8)>>>(Wihf, bihf, Wihb, bihb);
    k_enc_all<<<64, 256, smemE>>>(Whhf, bhhf, Whhb, bhhb);
    k_dec_all<<<DEC_BLKS, 256, smemD>>>(emb_dec, Wattn, battn, Wihd, Whhd,
                                        bihd, bhhd, Wout, bout, out_logp, out_att);
    k_mask<<<1, 32>>>(out_idx, out_mask);
    k_logp_final<<<(int)(((long)Bz*Tz*VDz/4 + 255)/256), 256>>>(out_logp);
}